// round 15
// baseline (speedup 1.0000x reference)
#include <cuda_runtime.h>
#include <cuda_fp16.h>
#include <cstdint>

#define NN 8192
#define IN_F 128
#define OUT_F 64
#define ALPHA 0.2f

#define TI 128                 // CTA row tile
#define BK 128                 // j per B stage
#define SPLITS 8
#define JSPAN (NN / SPLITS)    // 1024
#define NTI (NN / TI)          // 64

#define BSTRIDE 288            // bytes per n-row (256 data + 32 pad); conflict-free LDS.64
#define BTOTAL  (64 * BSTRIDE) // 18432

// Scratch
__device__ float g_s1[NN];
__device__ float g_s2[NN];
__device__ __half g_WhT[OUT_F * NN];      // transposed Wh, fp16 RN, FRAGMENT-PERMUTED j order
__device__ float g_accP[SPLITS][NN][OUT_F];
__device__ float g_lP[SPLITS][NN];

__device__ __forceinline__ uint32_t pack_half2(float x0, float x1) {
    __half2 h = __floats2half2_rn(x0, x1);
    return *(uint32_t*)&h;
}

__device__ __forceinline__ void mma16816f16(float* d,
                                            uint32_t a0, uint32_t a1, uint32_t a2, uint32_t a3,
                                            uint32_t b0, uint32_t b1) {
    asm volatile(
        "mma.sync.aligned.m16n8k16.row.col.f32.f16.f16.f32 "
        "{%0,%1,%2,%3}, {%4,%5,%6,%7}, {%8,%9}, {%0,%1,%2,%3};"
        : "+f"(d[0]), "+f"(d[1]), "+f"(d[2]), "+f"(d[3])
        : "r"(a0), "r"(a1), "r"(a2), "r"(a3), "r"(b0), "r"(b1));
}

// ---------------------------------------------------------------------------
// Kernel 1: Wh = h@W; s1 = Wh@a1; s2 = Wh@a2; WhT fp16 fragment-permuted.
// (unchanged from round 14)
// ---------------------------------------------------------------------------
__global__ __launch_bounds__(256) void wh_kernel(const float* __restrict__ h,
                                                 const float* __restrict__ W,
                                                 const float* __restrict__ a) {
    __shared__ float W_s[IN_F * OUT_F];
    __shared__ float h_s[4][IN_F];
    __shared__ float a_s[2 * OUT_F];
    __shared__ float red1[8], red2[8];
    __shared__ float tr[OUT_F][17];

    const int t = threadIdx.x;
    const int blockRow = blockIdx.x * 16;

    for (int i = t; i < IN_F * OUT_F; i += 256) W_s[i] = W[i];
    if (t < 2 * OUT_F) a_s[t] = a[t];

    const int g = t >> 6;
    const int c = t & 63;

    for (int rg = 0; rg < 4; ++rg) {
        const int rowBase = blockRow + rg * 4;
        __syncthreads();
        for (int i = t; i < 4 * IN_F; i += 256)
            h_s[i >> 7][i & 127] = h[(size_t)(rowBase + (i >> 7)) * IN_F + (i & 127)];
        __syncthreads();

        float acc = 0.f;
#pragma unroll 8
        for (int k = 0; k < IN_F; ++k)
            acc += h_s[g][k] * W_s[k * OUT_F + c];

        tr[c][rg * 4 + g] = acc;

        float v1 = acc * a_s[c];
        float v2 = acc * a_s[OUT_F + c];
#pragma unroll
        for (int off = 16; off > 0; off >>= 1) {
            v1 += __shfl_down_sync(0xffffffffu, v1, off);
            v2 += __shfl_down_sync(0xffffffffu, v2, off);
        }
        if ((t & 31) == 0) { red1[t >> 5] = v1; red2[t >> 5] = v2; }
        __syncthreads();
        if (t < 4) {
            g_s1[rowBase + t] = red1[2 * t] + red1[2 * t + 1];
            g_s2[rowBase + t] = red2[2 * t] + red2[2 * t + 1];
        }
    }
    __syncthreads();

    // fragment-permuted fp16 write-out.
    {
        const int cc = t >> 2;
        const int q = t & 3;
        float v[4];
#pragma unroll
        for (int i = 0; i < 4; ++i) v[i] = tr[cc][q * 4 + i];
        const int m0 = 2 * q, m1 = 2 * q + 1;
        const int p0 = 4 * (m0 & 3) + 2 * (m0 >> 2);
        const int p1 = 4 * (m1 & 3) + 2 * (m1 >> 2);
        size_t base = (size_t)cc * NN + blockRow;
        *(uint32_t*)&g_WhT[base + p0] = pack_half2(v[0], v[1]);
        *(uint32_t*)&g_WhT[base + p1] = pack_half2(v[2], v[3]);
    }
}

// ---------------------------------------------------------------------------
// Kernel 2: mma.sync fp16 attention — MUFU-free inner loop:
//   exp(lrelu(s1+s2)) = max(exp(s1)exp(s2), exp(a*s1)exp(a*s2))
// E2/F2 precomputed per span in smem; E1/F1 per row in registers.
// grid=(64 i-tiles, 8 splits), 8 warps.
// ---------------------------------------------------------------------------
__global__ void __launch_bounds__(256) attn_kernel(const int* __restrict__ adj) {
    __shared__ __align__(16) unsigned char Bs[BTOTAL];   // 64 rows x 288B
    __shared__ __align__(16) float E2_s[JSPAN];
    __shared__ __align__(16) float F2_s[JSPAN];

    const int t = threadIdx.x;
    const int wid = t >> 5;
    const int lane = t & 31;
    const int qr = lane >> 2;      // 0..7
    const int qm = lane & 3;       // 0..3

    const int iBase = blockIdx.x * TI;
    const int split = blockIdx.y;
    const int jStart = split * JSPAN;

    const int r0 = wid * 16 + qr;      // local row for a0/a2
    const int r1 = r0 + 8;             // a1/a3
    const float s1r0 = g_s1[iBase + r0];
    const float s1r1 = g_s1[iBase + r1];
    const float E1_0 = __expf(s1r0), F1_0 = __expf(ALPHA * s1r0);
    const float E1_1 = __expf(s1r1), F1_1 = __expf(ALPHA * s1r1);
    const int* __restrict__ row0 = adj + (size_t)(iBase + r0) * NN;
    const int* __restrict__ row1 = adj + (size_t)(iBase + r1) * NN;

    // prologue: exp tables for the j-span (once; 4 MUFU pairs per thread)
#pragma unroll
    for (int it = 0; it < 4; ++it) {
        int idx = it * 256 + t;
        float v = g_s2[jStart + idx];
        E2_s[idx] = __expf(v);
        F2_s[idx] = __expf(ALPHA * v);
    }

    float d[8][4];
#pragma unroll
    for (int nt = 0; nt < 8; ++nt)
#pragma unroll
        for (int i = 0; i < 4; ++i) d[nt][i] = 0.f;
    float lsum0 = 0.f, lsum1 = 0.f;

    const unsigned char* bLane = Bs + qr * BSTRIDE + qm * 8;   // per-lane B base

    for (int stage = 0; stage < JSPAN / BK; ++stage) {
        const int jStage = jStart + stage * BK;

        __syncthreads();   // prior MMAs done before Bs overwrite; stage0: E2/F2 ready

        // ---- load B stage: WhT fp16 (fragment order), 64 n-rows x 256B data
        for (int idx = t; idx < 1024; idx += 256) {
            int n = idx >> 4;              // 0..63
            int seg = idx & 15;            // 16B segment
            const __half* gsrc = g_WhT + (size_t)n * NN + jStage;
            uint4 v = ((const uint4*)gsrc)[seg];
            *(uint4*)(Bs + n * BSTRIDE + seg * 16) = v;
        }
        __syncthreads();

        // ---- 8 chunks of 16 j
#pragma unroll 2
        for (int c = 0; c < 8; ++c) {
            const int jc = stage * BK + c * 16 + 2 * qm;   // local j (within span)
            const int gj = jStage + c * 16 + 2 * qm;       // global j

            int2 A0 = __ldg((const int2*)(row0 + gj));
            int2 A2 = __ldg((const int2*)(row0 + gj + 8));
            int2 A1 = __ldg((const int2*)(row1 + gj));
            int2 A3 = __ldg((const int2*)(row1 + gj + 8));
            float2 E2a = *(const float2*)&E2_s[jc];
            float2 E2b = *(const float2*)&E2_s[jc + 8];
            float2 F2a = *(const float2*)&F2_s[jc];
            float2 F2b = *(const float2*)&F2_s[jc + 8];

            float p00, p01, p02, p03, p10, p11, p12, p13;
            p00 = fmaxf(E1_0 * E2a.x, F1_0 * F2a.x); p00 = (A0.x > 0) ? p00 : 0.f;
            p01 = fmaxf(E1_0 * E2a.y, F1_0 * F2a.y); p01 = (A0.y > 0) ? p01 : 0.f;
            p02 = fmaxf(E1_0 * E2b.x, F1_0 * F2b.x); p02 = (A2.x > 0) ? p02 : 0.f;
            p03 = fmaxf(E1_0 * E2b.y, F1_0 * F2b.y); p03 = (A2.y > 0) ? p03 : 0.f;
            p10 = fmaxf(E1_1 * E2a.x, F1_1 * F2a.x); p10 = (A1.x > 0) ? p10 : 0.f;
            p11 = fmaxf(E1_1 * E2a.y, F1_1 * F2a.y); p11 = (A1.y > 0) ? p11 : 0.f;
            p12 = fmaxf(E1_1 * E2b.x, F1_1 * F2b.x); p12 = (A3.x > 0) ? p12 : 0.f;
            p13 = fmaxf(E1_1 * E2b.y, F1_1 * F2b.y); p13 = (A3.y > 0) ? p13 : 0.f;

            lsum0 += (p00 + p01) + (p02 + p03);
            lsum1 += (p10 + p11) + (p12 + p13);

            uint32_t a0 = pack_half2(p00, p01), a2 = pack_half2(p02, p03);
            uint32_t a1 = pack_half2(p10, p11), a3 = pack_half2(p12, p13);

            const unsigned char* bp = bLane + c * 32;
#pragma unroll
            for (int nt = 0; nt < 8; ++nt) {
                uint2 b = *(const uint2*)(bp + nt * 8 * BSTRIDE);   // {b0, b1} contiguous
                mma16816f16(d[nt], a0, a1, a2, a3, b.x, b.y);
            }
        }
    }

    // ---- row sums: reduce across the 4 lanes of each quad-column group
    lsum0 += __shfl_xor_sync(0xffffffffu, lsum0, 1);
    lsum0 += __shfl_xor_sync(0xffffffffu, lsum0, 2);
    lsum1 += __shfl_xor_sync(0xffffffffu, lsum1, 1);
    lsum1 += __shfl_xor_sync(0xffffffffu, lsum1, 2);
    if (qm == 0) {
        g_lP[split][iBase + r0] = lsum0;
        g_lP[split][iBase + r1] = lsum1;
    }

    // ---- write partials: d[nt] = rows (r0, r1), cols nt*8 + 2*qm + {0,1}
    {
        float* base0 = &g_accP[split][iBase + r0][0];
        float* base1 = &g_accP[split][iBase + r1][0];
#pragma unroll
        for (int nt = 0; nt < 8; ++nt) {
            int cb = nt * 8 + 2 * qm;
            *(float2*)&base0[cb] = make_float2(d[nt][0], d[nt][1]);
            *(float2*)&base1[cb] = make_float2(d[nt][2], d[nt][3]);
        }
    }
}

// ---------------------------------------------------------------------------
// Kernel 3: sum split partials -> normalize -> ELU.
// ---------------------------------------------------------------------------
__global__ __launch_bounds__(256) void combine_kernel(float* __restrict__ out) {
    __shared__ float linv_s[16];
    const int t = threadIdx.x;
    const int rowBase = blockIdx.x * 16;

    if (t < 16) {
        int row = rowBase + t;
        float L = 0.f;
#pragma unroll
        for (int s = 0; s < SPLITS; ++s) L += g_lP[s][row];
        linv_s[t] = 1.f / L;
    }
    __syncthreads();

    const int rr = t >> 4;
    const int c4 = t & 15;
    const int row = rowBase + rr;

    float4 acc = make_float4(0.f, 0.f, 0.f, 0.f);
#pragma unroll
    for (int s = 0; s < SPLITS; ++s) {
        float4 v = *(const float4*)&g_accP[s][row][c4 * 4];
        acc.x += v.x; acc.y += v.y; acc.z += v.z; acc.w += v.w;
    }
    float li = linv_s[rr];
    float x0 = acc.x * li, x1 = acc.y * li, x2 = acc.z * li, x3 = acc.w * li;
    x0 = (x0 > 0.f) ? x0 : expm1f(x0);
    x1 = (x1 > 0.f) ? x1 : expm1f(x1);
    x2 = (x2 > 0.f) ? x2 : expm1f(x2);
    x3 = (x3 > 0.f) ? x3 : expm1f(x3);
    *(float4*)&out[(size_t)row * OUT_F + c4 * 4] = make_float4(x0, x1, x2, x3);
}

// ---------------------------------------------------------------------------
extern "C" void kernel_launch(void* const* d_in, const int* in_sizes, int n_in,
                              void* d_out, int out_size) {
    const float* h   = (const float*)d_in[0];   // 8192 x 128
    const int*   adj = (const int*)d_in[1];     // 8192 x 8192
    const float* W   = (const float*)d_in[2];   // 128 x 64
    const float* a   = (const float*)d_in[3];   // 128 x 1
    float* out = (float*)d_out;                 // 8192 x 64

    wh_kernel<<<NN / 16, 256>>>(h, W, a);
    attn_kernel<<<dim3(NTI, SPLITS), 256>>>(adj);
    combine_kernel<<<NN / 16, 256>>>(out);
}

// round 16
// speedup vs baseline: 1.1570x; 1.1570x over previous
#include <cuda_runtime.h>
#include <cuda_fp16.h>
#include <cstdint>

#define NN 8192
#define IN_F 128
#define OUT_F 64
#define ALPHA 0.2f

#define TI 128                 // CTA row tile
#define BK 128                 // j per B stage
#define SPLITS 8
#define JSPAN (NN / SPLITS)    // 1024
#define NTI (NN / TI)          // 64

#define BSTRIDE 288            // bytes per n-row (256 data + 32 pad); conflict-free LDS.64
#define BTOTAL  (64 * BSTRIDE) // 18432

// Scratch
__device__ float g_s1[NN];
__device__ float g_s2[NN];
__device__ __half g_WhT[OUT_F * NN];      // transposed Wh, fp16 RN, FRAGMENT-PERMUTED j order
__device__ float g_accP[SPLITS][NN][OUT_F];
__device__ float g_lP[SPLITS][NN];

__device__ __forceinline__ uint32_t pack_half2(float x0, float x1) {
    __half2 h = __floats2half2_rn(x0, x1);
    return *(uint32_t*)&h;
}

__device__ __forceinline__ void mma16816f16(float* d,
                                            uint32_t a0, uint32_t a1, uint32_t a2, uint32_t a3,
                                            uint32_t b0, uint32_t b1) {
    asm volatile(
        "mma.sync.aligned.m16n8k16.row.col.f32.f16.f16.f32 "
        "{%0,%1,%2,%3}, {%4,%5,%6,%7}, {%8,%9}, {%0,%1,%2,%3};"
        : "+f"(d[0]), "+f"(d[1]), "+f"(d[2]), "+f"(d[3])
        : "r"(a0), "r"(a1), "r"(a2), "r"(a3), "r"(b0), "r"(b1));
}

// ---------------------------------------------------------------------------
// Kernel 1: Wh = h@W; s1 = Wh@a1; s2 = Wh@a2; WhT fp16 fragment-permuted.
// k-loop split into 4 independent accumulators (breaks 512-cycle RAW chain).
// ---------------------------------------------------------------------------
__global__ __launch_bounds__(256) void wh_kernel(const float* __restrict__ h,
                                                 const float* __restrict__ W,
                                                 const float* __restrict__ a) {
    __shared__ float W_s[IN_F * OUT_F];
    __shared__ float h_s[4][IN_F];
    __shared__ float a_s[2 * OUT_F];
    __shared__ float red1[8], red2[8];
    __shared__ float tr[OUT_F][17];

    const int t = threadIdx.x;
    const int blockRow = blockIdx.x * 16;

    for (int i = t; i < IN_F * OUT_F; i += 256) W_s[i] = W[i];
    if (t < 2 * OUT_F) a_s[t] = a[t];

    const int g = t >> 6;
    const int c = t & 63;

    for (int rg = 0; rg < 4; ++rg) {
        const int rowBase = blockRow + rg * 4;
        __syncthreads();
        for (int i = t; i < 4 * IN_F; i += 256)
            h_s[i >> 7][i & 127] = h[(size_t)(rowBase + (i >> 7)) * IN_F + (i & 127)];
        __syncthreads();

        float acc0 = 0.f, acc1 = 0.f, acc2 = 0.f, acc3 = 0.f;
#pragma unroll
        for (int k = 0; k < IN_F; k += 4) {
            acc0 += h_s[g][k + 0] * W_s[(k + 0) * OUT_F + c];
            acc1 += h_s[g][k + 1] * W_s[(k + 1) * OUT_F + c];
            acc2 += h_s[g][k + 2] * W_s[(k + 2) * OUT_F + c];
            acc3 += h_s[g][k + 3] * W_s[(k + 3) * OUT_F + c];
        }
        float acc = (acc0 + acc1) + (acc2 + acc3);

        tr[c][rg * 4 + g] = acc;

        float v1 = acc * a_s[c];
        float v2 = acc * a_s[OUT_F + c];
#pragma unroll
        for (int off = 16; off > 0; off >>= 1) {
            v1 += __shfl_down_sync(0xffffffffu, v1, off);
            v2 += __shfl_down_sync(0xffffffffu, v2, off);
        }
        if ((t & 31) == 0) { red1[t >> 5] = v1; red2[t >> 5] = v2; }
        __syncthreads();
        if (t < 4) {
            g_s1[rowBase + t] = red1[2 * t] + red1[2 * t + 1];
            g_s2[rowBase + t] = red2[2 * t] + red2[2 * t + 1];
        }
    }
    __syncthreads();

    // fragment-permuted fp16 write-out.
    {
        const int cc = t >> 2;
        const int q = t & 3;
        float v[4];
#pragma unroll
        for (int i = 0; i < 4; ++i) v[i] = tr[cc][q * 4 + i];
        const int m0 = 2 * q, m1 = 2 * q + 1;
        const int p0 = 4 * (m0 & 3) + 2 * (m0 >> 2);
        const int p1 = 4 * (m1 & 3) + 2 * (m1 >> 2);
        size_t base = (size_t)cc * NN + blockRow;
        *(uint32_t*)&g_WhT[base + p0] = pack_half2(v[0], v[1]);
        *(uint32_t*)&g_WhT[base + p1] = pack_half2(v[2], v[3]);
    }
}

// ---------------------------------------------------------------------------
// Kernel 2: mma.sync fp16 attention (round-14 champion body; adj via __ldcs
// streaming loads to keep L2 for WhT/accP). grid=(64, 8), 8 warps.
// ---------------------------------------------------------------------------
__global__ void __launch_bounds__(256) attn_kernel(const int* __restrict__ adj) {
    __shared__ __align__(16) unsigned char Bs[BTOTAL];   // 64 rows x 288B
    __shared__ __align__(16) float s2_s[JSPAN];

    const int t = threadIdx.x;
    const int wid = t >> 5;
    const int lane = t & 31;
    const int qr = lane >> 2;      // 0..7
    const int qm = lane & 3;       // 0..3

    const int iBase = blockIdx.x * TI;
    const int split = blockIdx.y;
    const int jStart = split * JSPAN;

    const int r0 = wid * 16 + qr;      // local row for a0/a2
    const int r1 = r0 + 8;             // a1/a3
    const float s1r0 = g_s1[iBase + r0];
    const float s1r1 = g_s1[iBase + r1];
    const int* __restrict__ row0 = adj + (size_t)(iBase + r0) * NN;
    const int* __restrict__ row1 = adj + (size_t)(iBase + r1) * NN;

    // s2 span -> smem
    {
        const float4* src = (const float4*)&g_s2[jStart];
        ((float4*)s2_s)[t] = src[t];
    }

    float d[8][4];
#pragma unroll
    for (int nt = 0; nt < 8; ++nt)
#pragma unroll
        for (int i = 0; i < 4; ++i) d[nt][i] = 0.f;
    float lsum0 = 0.f, lsum1 = 0.f;

    const unsigned char* bLane = Bs + qr * BSTRIDE + qm * 8;   // per-lane B base

    for (int stage = 0; stage < JSPAN / BK; ++stage) {
        const int jStage = jStart + stage * BK;

        __syncthreads();   // prior MMAs done before overwriting Bs (also covers s2 on stage 0)

        // ---- load B stage: WhT fp16 (fragment order), 64 n-rows x 256B data
        for (int idx = t; idx < 1024; idx += 256) {
            int n = idx >> 4;              // 0..63
            int seg = idx & 15;            // 16B segment
            const __half* gsrc = g_WhT + (size_t)n * NN + jStage;
            uint4 v = ((const uint4*)gsrc)[seg];
            *(uint4*)(Bs + n * BSTRIDE + seg * 16) = v;
        }
        __syncthreads();

        // ---- 8 chunks of 16 j
#pragma unroll 2
        for (int c = 0; c < 8; ++c) {
            const int jc = stage * BK + c * 16 + 2 * qm;   // local j (within span)
            const int gj = jStage + c * 16 + 2 * qm;       // global j

            int2 A0 = __ldcs((const int2*)(row0 + gj));
            int2 A2 = __ldcs((const int2*)(row0 + gj + 8));
            int2 A1 = __ldcs((const int2*)(row1 + gj));
            int2 A3 = __ldcs((const int2*)(row1 + gj + 8));
            float2 s2a = *(const float2*)&s2_s[jc];
            float2 s2b = *(const float2*)&s2_s[jc + 8];

            float e, p00, p01, p02, p03, p10, p11, p12, p13;
            e = s1r0 + s2a.x; e = fmaxf(e, ALPHA * e); p00 = (A0.x > 0) ? __expf(e) : 0.f;
            e = s1r0 + s2a.y; e = fmaxf(e, ALPHA * e); p01 = (A0.y > 0) ? __expf(e) : 0.f;
            e = s1r0 + s2b.x; e = fmaxf(e, ALPHA * e); p02 = (A2.x > 0) ? __expf(e) : 0.f;
            e = s1r0 + s2b.y; e = fmaxf(e, ALPHA * e); p03 = (A2.y > 0) ? __expf(e) : 0.f;
            e = s1r1 + s2a.x; e = fmaxf(e, ALPHA * e); p10 = (A1.x > 0) ? __expf(e) : 0.f;
            e = s1r1 + s2a.y; e = fmaxf(e, ALPHA * e); p11 = (A1.y > 0) ? __expf(e) : 0.f;
            e = s1r1 + s2b.x; e = fmaxf(e, ALPHA * e); p12 = (A3.x > 0) ? __expf(e) : 0.f;
            e = s1r1 + s2b.y; e = fmaxf(e, ALPHA * e); p13 = (A3.y > 0) ? __expf(e) : 0.f;

            lsum0 += (p00 + p01) + (p02 + p03);
            lsum1 += (p10 + p11) + (p12 + p13);

            uint32_t a0 = pack_half2(p00, p01), a2 = pack_half2(p02, p03);
            uint32_t a1 = pack_half2(p10, p11), a3 = pack_half2(p12, p13);

            const unsigned char* bp = bLane + c * 32;
#pragma unroll
            for (int nt = 0; nt < 8; ++nt) {
                uint2 b = *(const uint2*)(bp + nt * 8 * BSTRIDE);   // {b0, b1} contiguous
                mma16816f16(d[nt], a0, a1, a2, a3, b.x, b.y);
            }
        }
    }

    // ---- row sums: reduce across the 4 lanes of each quad-column group
    lsum0 += __shfl_xor_sync(0xffffffffu, lsum0, 1);
    lsum0 += __shfl_xor_sync(0xffffffffu, lsum0, 2);
    lsum1 += __shfl_xor_sync(0xffffffffu, lsum1, 1);
    lsum1 += __shfl_xor_sync(0xffffffffu, lsum1, 2);
    if (qm == 0) {
        g_lP[split][iBase + r0] = lsum0;
        g_lP[split][iBase + r1] = lsum1;
    }

    // ---- write partials: d[nt] = rows (r0, r1), cols nt*8 + 2*qm + {0,1}
    {
        float* base0 = &g_accP[split][iBase + r0][0];
        float* base1 = &g_accP[split][iBase + r1][0];
#pragma unroll
        for (int nt = 0; nt < 8; ++nt) {
            int cb = nt * 8 + 2 * qm;
            *(float2*)&base0[cb] = make_float2(d[nt][0], d[nt][1]);
            *(float2*)&base1[cb] = make_float2(d[nt][2], d[nt][3]);
        }
    }
}

// ---------------------------------------------------------------------------
// Kernel 3: sum split partials -> normalize -> ELU.
// ---------------------------------------------------------------------------
__global__ __launch_bounds__(256) void combine_kernel(float* __restrict__ out) {
    __shared__ float linv_s[16];
    const int t = threadIdx.x;
    const int rowBase = blockIdx.x * 16;

    if (t < 16) {
        int row = rowBase + t;
        float L = 0.f;
#pragma unroll
        for (int s = 0; s < SPLITS; ++s) L += g_lP[s][row];
        linv_s[t] = 1.f / L;
    }
    __syncthreads();

    const int rr = t >> 4;
    const int c4 = t & 15;
    const int row = rowBase + rr;

    float4 acc = make_float4(0.f, 0.f, 0.f, 0.f);
#pragma unroll
    for (int s = 0; s < SPLITS; ++s) {
        float4 v = *(const float4*)&g_accP[s][row][c4 * 4];
        acc.x += v.x; acc.y += v.y; acc.z += v.z; acc.w += v.w;
    }
    float li = linv_s[rr];
    float x0 = acc.x * li, x1 = acc.y * li, x2 = acc.z * li, x3 = acc.w * li;
    x0 = (x0 > 0.f) ? x0 : expm1f(x0);
    x1 = (x1 > 0.f) ? x1 : expm1f(x1);
    x2 = (x2 > 0.f) ? x2 : expm1f(x2);
    x3 = (x3 > 0.f) ? x3 : expm1f(x3);
    *(float4*)&out[(size_t)row * OUT_F + c4 * 4] = make_float4(x0, x1, x2, x3);
}

// ---------------------------------------------------------------------------
extern "C" void kernel_launch(void* const* d_in, const int* in_sizes, int n_in,
                              void* d_out, int out_size) {
    const float* h   = (const float*)d_in[0];   // 8192 x 128
    const int*   adj = (const int*)d_in[1];     // 8192 x 8192
    const float* W   = (const float*)d_in[2];   // 128 x 64
    const float* a   = (const float*)d_in[3];   // 128 x 1
    float* out = (float*)d_out;                 // 8192 x 64

    wh_kernel<<<NN / 16, 256>>>(h, W, a);
    attn_kernel<<<dim3(NTI, SPLITS), 256>>>(adj);
    combine_kernel<<<NN / 16, 256>>>(out);
}